// round 9
// baseline (speedup 1.0000x reference)
#include <cuda_runtime.h>
#include <cuda_bf16.h>
#include <cstdint>

#define NN 100000
#define NE 640000
#define NL 100000
#define SCAN_BLK 512
#define NSCAN ((NN + SCAN_BLK - 1) / SCAN_BLK)

// Scratch (device globals: allocation-free rule)
__device__ uint32_t g_a1hi[(size_t)NN * 128];  // A1 = [mean | x], bf16 hi, permuted (K=256)
__device__ uint32_t g_a1lo[(size_t)NN * 128];  // bf16 lo
__device__ float g_h[(size_t)NN * 128];
__device__ float g_pq[(size_t)NN * 128];       // [p | q] = h @ [W2l | W2r]^T
__device__ float g_z[(size_t)NN * 64];
// CSR scratch
__device__ int g_deg[NN];
__device__ int g_excl[NN];
__device__ int g_bsum[NSCAN];
__device__ int g_boff[NSCAN];
__device__ int g_rowptr[NN + 1];
__device__ int g_cursor[NN];
__device__ int g_srcs[NE];

// ---------------------------------------------------------------------------
__device__ __forceinline__ uint32_t smem_u32(const void* p) {
    uint32_t a;
    asm("{ .reg .u64 t; cvta.to.shared.u64 t, %1; cvt.u32.u64 %0, t; }" : "=r"(a) : "l"(p));
    return a;
}

__device__ __forceinline__ void cp_async16(uint32_t saddr, const void* gaddr, int src_size) {
    asm volatile("cp.async.cg.shared.global [%0], [%1], 16, %2;"
                 :: "r"(saddr), "l"(gaddr), "r"(src_size) : "memory");
}
#define CP_COMMIT() asm volatile("cp.async.commit_group;" ::: "memory")
#define CP_WAIT(N)  asm volatile("cp.async.wait_group %0;" :: "n"(N) : "memory")

// bf16 hi/lo split of a float pair, packed as 2x u32 (bf16x2)
__device__ __forceinline__ void split2(float a, float b, uint32_t& hi, uint32_t& lo) {
    __nv_bfloat162 h = __floats2bfloat162_rn(a, b);
    hi = *reinterpret_cast<uint32_t*>(&h);
    __nv_bfloat162 l = __floats2bfloat162_rn(a - __low2float(h), b - __high2float(h));
    lo = *reinterpret_cast<uint32_t*>(&l);
}

// m16n8k16 bf16 mma, fp32 accumulate in place (row.col)
__device__ __forceinline__ void mma16816(float* c, const uint32_t* a, uint32_t b0, uint32_t b1) {
    asm volatile(
        "mma.sync.aligned.m16n8k16.row.col.f32.bf16.bf16.f32 "
        "{%0,%1,%2,%3}, {%4,%5,%6,%7}, {%8,%9}, {%0,%1,%2,%3};"
        : "+f"(c[0]), "+f"(c[1]), "+f"(c[2]), "+f"(c[3])
        : "r"(a[0]), "r"(a[1]), "r"(a[2]), "r"(a[3]), "r"(b0), "r"(b1));
}

// k16-group word permutation: word w (0..7 in group) -> u32 position
__device__ __forceinline__ int wperm(int w7) { return ((w7 & 3) << 1) | (w7 >> 2); }
// u32 index within a permuted row for global word index w
__device__ __forceinline__ int widx(int w) { return ((w >> 3) << 3) + wperm(w & 7); }

// fp32 A-stage geometry (GEMM2)
#define ASTR 288
#define ASZ  (128 * ASTR)
// bf16 A-stage geometry (GEMM1): 128B data + 32B pad -> conflict-min LDS.64
#define A1STR 160
#define A1SZ  (128 * A1STR)        // one hi or lo buffer = 20480 B

// ===========================================================================
// GEMM1 (pre-split A): h = relu( A1 @ [W1l;W1r]^T + b1 ),  A1 rows = K=256
// bf16 hi/lo permuted in global; B resident bf16 hi/lo permuted in smem.
// 512 threads / 16 warps, warp tile 16x64, persistent grid.
// ===========================================================================
__device__ __forceinline__ void prefetch1(
    int it, int bid, int grid, int M,
    const uint8_t* __restrict__ A1hi, const uint8_t* __restrict__ A1lo,
    uint32_t sA_u32, int tid)
{
    const int tIdx = it >> 2;
    const int chunk = it & 3;
    const int row0 = (bid + tIdx * grid) << 7;
    const uint32_t abase = sA_u32 + (it & 1) * (2 * A1SZ);
#pragma unroll
    for (int s = 0; s < 4; ++s) {
        int seg = s * 512 + tid;            // 0..2047
        int buf = seg >> 10;                // 0=hi, 1=lo
        int r = (seg >> 3) & 127;
        int c16 = seg & 7;
        bool val = (row0 + r) < M;
        const uint8_t* base = buf ? A1lo : A1hi;
        const uint8_t* g = base + (val ? (((size_t)(row0 + r) << 9) + chunk * 128 + c16 * 16) : 0);
        cp_async16(abase + buf * A1SZ + r * A1STR + c16 * 16, g, val ? 16 : 0);
    }
    CP_COMMIT();
}

__global__ void __launch_bounds__(512, 1)
pgemm1_kernel(const uint8_t* __restrict__ A1hi, const uint8_t* __restrict__ A1lo,
              const float* __restrict__ Wa, const float* __restrict__ Wb,
              const float* __restrict__ bias,
              float* __restrict__ out, int M)
{
    constexpr int K = 256;
    constexpr int BSTR = K * 2 + 32;       // 544
    constexpr int SB = 128 * BSTR;

    extern __shared__ uint8_t smem[];
    uint8_t* sBh = smem;
    uint8_t* sBl = smem + SB;
    uint8_t* sA  = smem + 2 * SB;          // [stage][hi|lo]

    const int tid = threadIdx.x, lane = tid & 31, wid = tid >> 5;
    const int warp_m = wid & 7, warp_n = wid >> 3;
    const int qrow = lane >> 2;
    const int bid = blockIdx.x, grid = gridDim.x;
    const uint32_t sA_u32 = smem_u32(smem) + 2 * SB;

    // ---- convert weights once: bf16 hi/lo, k16-group word-permuted ----
    for (int idx = tid; idx < 128 * (K / 4); idx += 512) {
        int row = idx / (K / 4);
        int k = (idx % (K / 4)) * 4;
        const float* wsrc = (k < 128) ? (Wa + (size_t)row * 128 + k)
                                      : (Wb + (size_t)row * 128 + k - 128);
        float4 v = __ldg(reinterpret_cast<const float4*>(wsrc));
        uint32_t h01, l01, h23, l23;
        split2(v.x, v.y, h01, l01);
        split2(v.z, v.w, h23, l23);
        const int base = row * BSTR + (k >> 4) * 32;
        const int km = k & 15;
        const int p0 = (km == 0) ? 0 : (km == 4) ? 16 : (km == 8) ? 4 : 20;
        *reinterpret_cast<uint32_t*>(sBh + base + p0)     = h01;
        *reinterpret_cast<uint32_t*>(sBh + base + p0 + 8) = h23;
        *reinterpret_cast<uint32_t*>(sBl + base + p0)     = l01;
        *reinterpret_cast<uint32_t*>(sBl + base + p0 + 8) = l23;
    }

    const int ntiles = (M + 127) >> 7;
    if (bid >= ntiles) return;
    const int nmine = (ntiles - bid + grid - 1) / grid;
    const int nIter = nmine * 4;

    float acc[8][4] = {};

    prefetch1(0, bid, grid, M, A1hi, A1lo, sA_u32, tid);

    for (int it = 0; it < nIter; ++it) {
        if (it) __syncthreads();
        if (it + 1 < nIter) {
            prefetch1(it + 1, bid, grid, M, A1hi, A1lo, sA_u32, tid);
            CP_WAIT(1);
        } else {
            CP_WAIT(0);
        }
        __syncthreads();

        const int tIdx = it >> 2, chunk = it & 3;
        const uint8_t* aSh = sA + (it & 1) * (2 * A1SZ);
        const uint8_t* aSl = aSh + A1SZ;

#pragma unroll
        for (int s = 0; s < 4; ++s) {
            const int rb = (warp_m * 16 + qrow) * A1STR + s * 32 + (lane & 3) * 8;
            uint2 h0 = *reinterpret_cast<const uint2*>(aSh + rb);
            uint2 h8 = *reinterpret_cast<const uint2*>(aSh + rb + 8 * A1STR);
            uint2 l0 = *reinterpret_cast<const uint2*>(aSl + rb);
            uint2 l8 = *reinterpret_cast<const uint2*>(aSl + rb + 8 * A1STR);
            uint32_t ah[4] = {h0.x, h8.x, h0.y, h8.y};
            uint32_t al[4] = {l0.x, l8.x, l0.y, l8.y};
            const int gk32 = (chunk * 4 + s) * 32 + (lane & 3) * 8;
#pragma unroll
            for (int j = 0; j < 8; ++j) {
                const int nb = (warp_n * 64 + j * 8 + qrow) * BSTR + gk32;
                uint2 bh = *reinterpret_cast<const uint2*>(sBh + nb);
                uint2 bl = *reinterpret_cast<const uint2*>(sBl + nb);
                mma16816(acc[j], ah, bh.x, bh.y);
                mma16816(acc[j], ah, bl.x, bl.y);
                mma16816(acc[j], al, bh.x, bh.y);
            }
        }

        if (chunk == 3) {
            const int row0 = (bid + tIdx * grid) << 7;
            const int r = row0 + warp_m * 16 + qrow;
#pragma unroll
            for (int j = 0; j < 8; ++j) {
                const int col = warp_n * 64 + j * 8 + (lane & 3) * 2;
                float2 bv = *reinterpret_cast<const float2*>(bias + col);
                float2 v0, v1;
                v0.x = fmaxf(acc[j][0] + bv.x, 0.f); v0.y = fmaxf(acc[j][1] + bv.y, 0.f);
                v1.x = fmaxf(acc[j][2] + bv.x, 0.f); v1.y = fmaxf(acc[j][3] + bv.y, 0.f);
                if (r < M)
                    *reinterpret_cast<float2*>(out + (size_t)r * 128 + col) = v0;
                if (r + 8 < M)
                    *reinterpret_cast<float2*>(out + (size_t)(r + 8) * 128 + col) = v1;
                acc[j][0] = acc[j][1] = acc[j][2] = acc[j][3] = 0.f;
            }
        }
    }
}

// ===========================================================================
// GEMM2 (R8 structure, fp32 A + in-loop split): pq = h @ [W2l|W2r]^T, K=128
// ===========================================================================
__device__ __forceinline__ void prefetch2(
    int it, int bid, int grid, int M,
    const float* __restrict__ A1, uint32_t sA_u32, int tid)
{
    const int tIdx = it >> 1;
    const int chunk = it & 1;
    const int row0 = (bid + tIdx * grid) << 7;
    const uint32_t abase = sA_u32 + (it & 1) * ASZ;
    const float* gbase = A1 + (size_t)row0 * 128 + chunk * 64;
#pragma unroll
    for (int s = 0; s < 4; ++s) {
        int seg = s * 512 + tid;
        int r = seg >> 4, c = seg & 15;
        bool val = (row0 + r) < M;
        const float* g = gbase + (val ? ((size_t)r * 128 + c * 4) : 0);
        cp_async16(abase + r * ASTR + c * 16, g, val ? 16 : 0);
    }
    CP_COMMIT();
}

__global__ void __launch_bounds__(512, 1)
pgemm2_kernel(const float* __restrict__ A1,
              const float* __restrict__ Wa, const float* __restrict__ Wb,
              float* __restrict__ out, int M)
{
    constexpr int K = 128;
    constexpr int BSTR = K * 2 + 32;
    constexpr int SB = 128 * BSTR;

    extern __shared__ uint8_t smem[];
    uint8_t* sBh = smem;
    uint8_t* sBl = smem + SB;
    uint8_t* sA  = smem + 2 * SB;

    const int tid = threadIdx.x, lane = tid & 31, wid = tid >> 5;
    const int warp_m = wid & 7, warp_n = wid >> 3;
    const int qrow = lane >> 2;
    const int bid = blockIdx.x, grid = gridDim.x;
    const uint32_t sA_u32 = smem_u32(smem) + 2 * SB;

    for (int idx = tid; idx < 128 * (K / 4); idx += 512) {
        int row = idx / (K / 4);
        int k = (idx % (K / 4)) * 4;
        const float* wsrc = ((row < 64) ? (Wa + (size_t)row * 128)
                                        : (Wb + (size_t)(row - 64) * 128)) + k;
        float4 v = __ldg(reinterpret_cast<const float4*>(wsrc));
        uint32_t h01, l01, h23, l23;
        split2(v.x, v.y, h01, l01);
        split2(v.z, v.w, h23, l23);
        const int base = row * BSTR + (k >> 4) * 32;
        const int km = k & 15;
        const int p0 = (km == 0) ? 0 : (km == 4) ? 16 : (km == 8) ? 4 : 20;
        *reinterpret_cast<uint32_t*>(sBh + base + p0)     = h01;
        *reinterpret_cast<uint32_t*>(sBh + base + p0 + 8) = h23;
        *reinterpret_cast<uint32_t*>(sBl + base + p0)     = l01;
        *reinterpret_cast<uint32_t*>(sBl + base + p0 + 8) = l23;
    }

    const int ntiles = (M + 127) >> 7;
    if (bid >= ntiles) return;
    const int nmine = (ntiles - bid + grid - 1) / grid;
    const int nIter = nmine * 2;

    float acc[8][4] = {};

    prefetch2(0, bid, grid, M, A1, sA_u32, tid);

    for (int it = 0; it < nIter; ++it) {
        if (it) __syncthreads();
        if (it + 1 < nIter) {
            prefetch2(it + 1, bid, grid, M, A1, sA_u32, tid);
            CP_WAIT(1);
        } else {
            CP_WAIT(0);
        }
        __syncthreads();

        const int tIdx = it >> 1, chunk = it & 1;
        const uint8_t* aS = sA + (it & 1) * ASZ;

#pragma unroll
        for (int s = 0; s < 4; ++s) {
            uint32_t ah[4], al[4];
            {
                const int rb = (warp_m * 16 + qrow) * ASTR + (s * 16 + (lane & 3) * 2) * 4;
                float2 p0 = *reinterpret_cast<const float2*>(aS + rb);
                float2 p8 = *reinterpret_cast<const float2*>(aS + rb + 8 * ASTR);
                float2 u0 = *reinterpret_cast<const float2*>(aS + rb + 32);
                float2 u8 = *reinterpret_cast<const float2*>(aS + rb + 8 * ASTR + 32);
                split2(p0.x, p0.y, ah[0], al[0]);
                split2(p8.x, p8.y, ah[1], al[1]);
                split2(u0.x, u0.y, ah[2], al[2]);
                split2(u8.x, u8.y, ah[3], al[3]);
            }
            const int gk32 = (chunk * 4 + s) * 32 + (lane & 3) * 8;
#pragma unroll
            for (int j = 0; j < 8; ++j) {
                const int nb = (warp_n * 64 + j * 8 + qrow) * BSTR + gk32;
                uint2 bh = *reinterpret_cast<const uint2*>(sBh + nb);
                uint2 bl = *reinterpret_cast<const uint2*>(sBl + nb);
                mma16816(acc[j], ah, bh.x, bh.y);
                mma16816(acc[j], ah, bl.x, bl.y);
                mma16816(acc[j], al, bh.x, bh.y);
            }
        }

        if (chunk == 1) {
            const int row0 = (bid + tIdx * grid) << 7;
            const int r = row0 + warp_m * 16 + qrow;
#pragma unroll
            for (int j = 0; j < 8; ++j) {
                const int col = warp_n * 64 + j * 8 + (lane & 3) * 2;
                float2 v0 = make_float2(acc[j][0], acc[j][1]);
                float2 v1 = make_float2(acc[j][2], acc[j][3]);
                if (r < M)
                    *reinterpret_cast<float2*>(out + (size_t)r * 128 + col) = v0;
                if (r + 8 < M)
                    *reinterpret_cast<float2*>(out + (size_t)(r + 8) * 128 + col) = v1;
                acc[j][0] = acc[j][1] = acc[j][2] = acc[j][3] = 0.f;
            }
        }
    }
}

// ===========================================================================
// CSR build: histogram -> 3-phase exclusive scan -> slot fill
// ===========================================================================
__global__ void zero_deg_kernel(int* deg, int n) {
    int i = blockIdx.x * blockDim.x + threadIdx.x;
    if (i < n) deg[i] = 0;
}

__global__ void hist_kernel(const int* __restrict__ ei, int* __restrict__ deg, int E) {
    int e = blockIdx.x * blockDim.x + threadIdx.x;
    if (e >= E) return;
    int d = __ldg(&ei[E + e]);
    if ((unsigned)d < NN) atomicAdd(&deg[d], 1);
}

__global__ void scan1_kernel(const int* __restrict__ deg, int* __restrict__ excl,
                             int* __restrict__ bsum, int n) {
    __shared__ int sh[SCAN_BLK];
    int b = blockIdx.x;
    int i = b * SCAN_BLK + threadIdx.x;
    int v = (i < n) ? deg[i] : 0;
    sh[threadIdx.x] = v;
    __syncthreads();
#pragma unroll
    for (int off = 1; off < SCAN_BLK; off <<= 1) {
        int t = (threadIdx.x >= off) ? sh[threadIdx.x - off] : 0;
        __syncthreads();
        sh[threadIdx.x] += t;
        __syncthreads();
    }
    if (i < n) excl[i] = sh[threadIdx.x] - v;
    if (threadIdx.x == SCAN_BLK - 1) bsum[b] = sh[SCAN_BLK - 1];
}

// parallel exclusive scan over NSCAN (<= 256) block sums, one block
__global__ void scan2_kernel(const int* __restrict__ bsum, int* __restrict__ boff, int nb) {
    __shared__ int sh[256];
    int t = threadIdx.x;
    int v = (t < nb) ? bsum[t] : 0;
    sh[t] = v;
    __syncthreads();
#pragma unroll
    for (int off = 1; off < 256; off <<= 1) {
        int u = (t >= off) ? sh[t - off] : 0;
        __syncthreads();
        sh[t] += u;
        __syncthreads();
    }
    if (t < nb) boff[t] = sh[t] - v;
}

__global__ void scan3_kernel(const int* __restrict__ excl, const int* __restrict__ boff,
                             int* __restrict__ rowptr, int* __restrict__ cursor, int n, int total) {
    int i = blockIdx.x * blockDim.x + threadIdx.x;
    if (i < n) {
        int v = excl[i] + boff[i / SCAN_BLK];
        rowptr[i] = v;
        cursor[i] = v;
    }
    if (i == 0) rowptr[n] = total;
}

__global__ void fill_kernel(const int* __restrict__ ei, int* __restrict__ cursor,
                            int* __restrict__ srcs, int E) {
    int e = blockIdx.x * blockDim.x + threadIdx.x;
    if (e >= E) return;
    int s = __ldg(&ei[e]);
    int d = __ldg(&ei[E + e]);
    if ((unsigned)s >= NN || (unsigned)d >= NN) return;
    int slot = atomicAdd(&cursor[d], 1);
    srcs[slot] = s;
}

// ===========================================================================
// agg1: warp per node. Computes mean of neighbor x rows AND converts the
// fused A1 row [mean | x_self] to permuted bf16 hi/lo (GEMM1-ready).
// ===========================================================================
__global__ void agg1_kernel(const float* __restrict__ x,
                            const int* __restrict__ rowptr,
                            const int* __restrict__ srcs,
                            uint32_t* __restrict__ a1hi,
                            uint32_t* __restrict__ a1lo) {
    int gid = blockIdx.x * blockDim.x + threadIdx.x;
    int n = gid >> 5, lane = gid & 31;
    if (n >= NN) return;
    int beg = __ldg(&rowptr[n]), end = __ldg(&rowptr[n + 1]);
    float4 acc = make_float4(0.f, 0.f, 0.f, 0.f);
    for (int i = beg; i < end; ++i) {
        int s = __ldg(&srcs[i]);
        float4 v = __ldg(reinterpret_cast<const float4*>(x + (size_t)s * 128) + lane);
        acc.x += v.x; acc.y += v.y; acc.z += v.z; acc.w += v.w;
    }
    float sc = 1.f / fmaxf((float)(end - beg), 1.f);
    acc.x *= sc; acc.y *= sc; acc.z *= sc; acc.w *= sc;

    uint32_t* rh = a1hi + (size_t)n * 128;
    uint32_t* rl = a1lo + (size_t)n * 128;
    uint32_t hi, lo;
    // mean part: words 2*lane, 2*lane+1
    split2(acc.x, acc.y, hi, lo);
    rh[widx(2 * lane)] = hi;     rl[widx(2 * lane)] = lo;
    split2(acc.z, acc.w, hi, lo);
    rh[widx(2 * lane + 1)] = hi; rl[widx(2 * lane + 1)] = lo;
    // self part: words 64 + 2*lane, 64 + 2*lane + 1
    float4 xv = __ldg(reinterpret_cast<const float4*>(x + (size_t)n * 128) + lane);
    split2(xv.x, xv.y, hi, lo);
    rh[widx(64 + 2 * lane)] = hi;     rl[widx(64 + 2 * lane)] = lo;
    split2(xv.z, xv.w, hi, lo);
    rh[widx(64 + 2 * lane + 1)] = hi; rl[widx(64 + 2 * lane + 1)] = lo;
}

// layer-2 aggregation of p fused with combine: z = mean_p + q + b2
__global__ void agg2z_kernel(const float* __restrict__ pq,
                             const int* __restrict__ rowptr,
                             const int* __restrict__ srcs,
                             const float* __restrict__ b2,
                             float* __restrict__ z) {
    int gid = blockIdx.x * blockDim.x + threadIdx.x;
    int n = gid >> 5, lane = gid & 31;
    if (n >= NN) return;
    int beg = __ldg(&rowptr[n]), end = __ldg(&rowptr[n + 1]);
    float2 acc = make_float2(0.f, 0.f);
    for (int i = beg; i < end; ++i) {
        int s = __ldg(&srcs[i]);
        float2 v = __ldg(reinterpret_cast<const float2*>(pq + (size_t)s * 128) + lane);
        acc.x += v.x; acc.y += v.y;
    }
    float sc = 1.f / fmaxf((float)(end - beg), 1.f);
    float2 q = __ldg(reinterpret_cast<const float2*>(pq + (size_t)n * 128 + 64) + lane);
    float2 bv = *reinterpret_cast<const float2*>(b2 + lane * 2);
    float2 r;
    r.x = fmaf(acc.x, sc, q.x + bv.x);
    r.y = fmaf(acc.y, sc, q.y + bv.y);
    *reinterpret_cast<float2*>(z + (size_t)n * 64 + lane * 2) = r;
}

// ===========================================================================
__global__ void decode_kernel(const float* __restrict__ z,
                              const int* __restrict__ eli,
                              float* __restrict__ out, int L) {
    int gid = blockIdx.x * blockDim.x + threadIdx.x;
    int e = gid >> 5;
    int lane = gid & 31;
    if (e >= L) return;
    int a = __ldg(&eli[e]);
    int b = __ldg(&eli[L + e]);
    float s = 0.f;
    if ((unsigned)a < NN && (unsigned)b < NN) {
        float2 va = *reinterpret_cast<const float2*>(z + (size_t)a * 64 + lane * 2);
        float2 vb = *reinterpret_cast<const float2*>(z + (size_t)b * 64 + lane * 2);
        s = va.x * vb.x + va.y * vb.y;
    }
#pragma unroll
    for (int off = 16; off > 0; off >>= 1)
        s += __shfl_xor_sync(0xFFFFFFFFu, s, off);
    if (lane == 0) out[e] = s;
}

// ===========================================================================
extern "C" void kernel_launch(void* const* d_in, const int* in_sizes, int n_in,
                              void* d_out, int out_size) {
    const float* x   = (const float*)d_in[0];
    const int*   ei  = (const int*)d_in[1];
    const int*   eli = (const int*)d_in[2];
    const float* W1l = (const float*)d_in[3];
    const float* b1  = (const float*)d_in[4];
    const float* W1r = (const float*)d_in[5];
    const float* W2l = (const float*)d_in[6];
    const float* b2  = (const float*)d_in[7];
    const float* W2r = (const float*)d_in[8];
    float* out = (float*)d_out;

    uint32_t *a1hi, *a1lo;
    float *h, *pq, *z;
    int *deg, *excl, *bsum, *boff, *rowptr, *cursor, *srcs;
    cudaGetSymbolAddress((void**)&a1hi, g_a1hi);
    cudaGetSymbolAddress((void**)&a1lo, g_a1lo);
    cudaGetSymbolAddress((void**)&h,   g_h);
    cudaGetSymbolAddress((void**)&pq,  g_pq);
    cudaGetSymbolAddress((void**)&z,   g_z);
    cudaGetSymbolAddress((void**)&deg, g_deg);
    cudaGetSymbolAddress((void**)&excl, g_excl);
    cudaGetSymbolAddress((void**)&bsum, g_bsum);
    cudaGetSymbolAddress((void**)&boff, g_boff);
    cudaGetSymbolAddress((void**)&rowptr, g_rowptr);
    cudaGetSymbolAddress((void**)&cursor, g_cursor);
    cudaGetSymbolAddress((void**)&srcs, g_srcs);

    const int smem1 = 2 * (128 * (256 * 2 + 32)) + 4 * A1SZ + 1024;   // 222,208
    const int smem2 = 2 * (128 * (128 * 2 + 32)) + 2 * ASZ + 1024;
    cudaFuncSetAttribute(pgemm1_kernel, cudaFuncAttributeMaxDynamicSharedMemorySize, smem1);
    cudaFuncSetAttribute(pgemm2_kernel, cudaFuncAttributeMaxDynamicSharedMemorySize, smem2);
    const int PGRID = 148;

    // ---- CSR build (shared by both layers) ----
    zero_deg_kernel<<<(NN + 255) / 256, 256>>>(deg, NN);
    hist_kernel<<<(NE + 255) / 256, 256>>>(ei, deg, NE);
    scan1_kernel<<<NSCAN, SCAN_BLK>>>(deg, excl, bsum, NN);
    scan2_kernel<<<1, 256>>>(bsum, boff, NSCAN);
    scan3_kernel<<<(NN + 255) / 256, 256>>>(excl, boff, rowptr, cursor, NN, NE);
    fill_kernel<<<(NE + 255) / 256, 256>>>(ei, cursor, srcs, NE);

    // ---- Layer 1 ----
    agg1_kernel<<<(NN * 32 + 255) / 256, 256>>>(x, rowptr, srcs, a1hi, a1lo);
    pgemm1_kernel<<<PGRID, 512, smem1>>>((const uint8_t*)a1hi, (const uint8_t*)a1lo,
                                         W1l, W1r, b1, h, NN);

    // ---- Layer 2 (projection-before-aggregation) ----
    pgemm2_kernel<<<PGRID, 512, smem2>>>(h, W2l, W2r, pq, NN);
    agg2z_kernel<<<(NN * 32 + 255) / 256, 256>>>(pq, rowptr, srcs, b2, z);

    // ---- Decode ----
    decode_kernel<<<(NL * 32 + 255) / 256, 256>>>(z, eli, out, NL);
}

// round 10
// speedup vs baseline: 1.0158x; 1.0158x over previous
#include <cuda_runtime.h>
#include <cuda_bf16.h>
#include <cstdint>

#define NN 100000
#define NE 640000
#define NL 100000
#define SCAN_BLK 512
#define NSCAN ((NN + SCAN_BLK - 1) / SCAN_BLK)

// Scratch (device globals: allocation-free rule)
__device__ float g_agg[(size_t)NN * 128];     // layer-1 mean aggregate
__device__ float g_hpre[(size_t)NN * 128];    // x @ W1r^T (self term)
__device__ float g_h[(size_t)NN * 128];
__device__ float g_pq[(size_t)NN * 128];      // [p | q] = h @ [W2l | W2r]^T
__device__ float g_z[(size_t)NN * 64];
// CSR scratch
__device__ int g_deg[NN];
__device__ int g_excl[NN];
__device__ int g_bsum[NSCAN];
__device__ int g_boff[NSCAN];
__device__ int g_rowptr[NN + 1];
__device__ int g_cursor[NN];
__device__ int g_srcs[NE];

// ---------------------------------------------------------------------------
__device__ __forceinline__ uint32_t smem_u32(const void* p) {
    uint32_t a;
    asm("{ .reg .u64 t; cvta.to.shared.u64 t, %1; cvt.u32.u64 %0, t; }" : "=r"(a) : "l"(p));
    return a;
}

__device__ __forceinline__ void cp_async16(uint32_t saddr, const void* gaddr, int src_size) {
    asm volatile("cp.async.cg.shared.global [%0], [%1], 16, %2;"
                 :: "r"(saddr), "l"(gaddr), "r"(src_size) : "memory");
}
#define CP_COMMIT() asm volatile("cp.async.commit_group;" ::: "memory")
#define CP_WAIT(N)  asm volatile("cp.async.wait_group %0;" :: "n"(N) : "memory")

// bf16 hi/lo split of a float pair, packed as 2x u32 (bf16x2)
__device__ __forceinline__ void split2(float a, float b, uint32_t& hi, uint32_t& lo) {
    __nv_bfloat162 h = __floats2bfloat162_rn(a, b);
    hi = *reinterpret_cast<uint32_t*>(&h);
    __nv_bfloat162 l = __floats2bfloat162_rn(a - __low2float(h), b - __high2float(h));
    lo = *reinterpret_cast<uint32_t*>(&l);
}

// m16n8k16 bf16 mma, fp32 accumulate in place (row.col)
__device__ __forceinline__ void mma16816(float* c, const uint32_t* a, uint32_t b0, uint32_t b1) {
    asm volatile(
        "mma.sync.aligned.m16n8k16.row.col.f32.bf16.bf16.f32 "
        "{%0,%1,%2,%3}, {%4,%5,%6,%7}, {%8,%9}, {%0,%1,%2,%3};"
        : "+f"(c[0]), "+f"(c[1]), "+f"(c[2]), "+f"(c[3])
        : "r"(a[0]), "r"(a[1]), "r"(a[2]), "r"(a[3]), "r"(b0), "r"(b1));
}

#define ASTR 288
#define ASZ  (128 * ASTR)

// ===========================================================================
// Persistent K=128 tensor-core GEMM: out[m, 0:128] = epi( A[m,:] @ W^T )
// W rows: row<64 from Wa, else Wb (pass Wa=W, Wb=W+64*128 for a full 128-row W).
// EPI 0: identity. EPI 1: relu(acc + addend[m,col] + bias[col]).
// 512 threads / 16 warps, warp tile 16x64, cp.async 2-stage A pipeline,
// weights resident in smem as bf16 hi/lo (3-MMA split product).
// ===========================================================================
__device__ __forceinline__ void prefetchA(
    int it, int bid, int grid, int M,
    const float* __restrict__ A, uint32_t sA_u32, int tid)
{
    const int tIdx = it >> 1;
    const int chunk = it & 1;
    const int row0 = (bid + tIdx * grid) << 7;
    const uint32_t abase = sA_u32 + (it & 1) * ASZ;
    const float* gbase = A + (size_t)row0 * 128 + chunk * 64;
#pragma unroll
    for (int s = 0; s < 4; ++s) {
        int seg = s * 512 + tid;
        int r = seg >> 4, c = seg & 15;
        bool val = (row0 + r) < M;
        const float* g = gbase + (val ? ((size_t)r * 128 + c * 4) : 0);
        cp_async16(abase + r * ASTR + c * 16, g, val ? 16 : 0);
    }
    CP_COMMIT();
}

template <int EPI>
__global__ void __launch_bounds__(512, 1)
pgemmB_kernel(const float* __restrict__ A,
              const float* __restrict__ Wa, const float* __restrict__ Wb,
              const float* __restrict__ addend, const float* __restrict__ bias,
              float* __restrict__ out, int M)
{
    constexpr int K = 128;
    constexpr int BSTR = K * 2 + 32;
    constexpr int SB = 128 * BSTR;

    extern __shared__ uint8_t smem[];
    uint8_t* sBh = smem;
    uint8_t* sBl = smem + SB;
    uint8_t* sA  = smem + 2 * SB;

    const int tid = threadIdx.x, lane = tid & 31, wid = tid >> 5;
    const int warp_m = wid & 7, warp_n = wid >> 3;
    const int qrow = lane >> 2;
    const int bid = blockIdx.x, grid = gridDim.x;
    const uint32_t sA_u32 = smem_u32(smem) + 2 * SB;

    // convert weights once: bf16 hi/lo, k16-group word-permuted
    for (int idx = tid; idx < 128 * (K / 4); idx += 512) {
        int row = idx / (K / 4);
        int k = (idx % (K / 4)) * 4;
        const float* wsrc = ((row < 64) ? (Wa + (size_t)row * 128)
                                        : (Wb + (size_t)(row - 64) * 128)) + k;
        float4 v = __ldg(reinterpret_cast<const float4*>(wsrc));
        uint32_t h01, l01, h23, l23;
        split2(v.x, v.y, h01, l01);
        split2(v.z, v.w, h23, l23);
        const int base = row * BSTR + (k >> 4) * 32;
        const int km = k & 15;
        const int p0 = (km == 0) ? 0 : (km == 4) ? 16 : (km == 8) ? 4 : 20;
        *reinterpret_cast<uint32_t*>(sBh + base + p0)     = h01;
        *reinterpret_cast<uint32_t*>(sBh + base + p0 + 8) = h23;
        *reinterpret_cast<uint32_t*>(sBl + base + p0)     = l01;
        *reinterpret_cast<uint32_t*>(sBl + base + p0 + 8) = l23;
    }

    const int ntiles = (M + 127) >> 7;
    if (bid >= ntiles) return;
    const int nmine = (ntiles - bid + grid - 1) / grid;
    const int nIter = nmine * 2;

    float acc[8][4] = {};

    prefetchA(0, bid, grid, M, A, sA_u32, tid);

    for (int it = 0; it < nIter; ++it) {
        if (it) __syncthreads();
        if (it + 1 < nIter) {
            prefetchA(it + 1, bid, grid, M, A, sA_u32, tid);
            CP_WAIT(1);
        } else {
            CP_WAIT(0);
        }
        __syncthreads();

        const int tIdx = it >> 1, chunk = it & 1;
        const uint8_t* aS = sA + (it & 1) * ASZ;

#pragma unroll
        for (int s = 0; s < 4; ++s) {
            uint32_t ah[4], al[4];
            {
                const int rb = (warp_m * 16 + qrow) * ASTR + (s * 16 + (lane & 3) * 2) * 4;
                float2 p0 = *reinterpret_cast<const float2*>(aS + rb);
                float2 p8 = *reinterpret_cast<const float2*>(aS + rb + 8 * ASTR);
                float2 u0 = *reinterpret_cast<const float2*>(aS + rb + 32);
                float2 u8 = *reinterpret_cast<const float2*>(aS + rb + 8 * ASTR + 32);
                split2(p0.x, p0.y, ah[0], al[0]);
                split2(p8.x, p8.y, ah[1], al[1]);
                split2(u0.x, u0.y, ah[2], al[2]);
                split2(u8.x, u8.y, ah[3], al[3]);
            }
            const int gk32 = (chunk * 4 + s) * 32 + (lane & 3) * 8;
#pragma unroll
            for (int j = 0; j < 8; ++j) {
                const int nb = (warp_n * 64 + j * 8 + qrow) * BSTR + gk32;
                uint2 bh = *reinterpret_cast<const uint2*>(sBh + nb);
                uint2 bl = *reinterpret_cast<const uint2*>(sBl + nb);
                mma16816(acc[j], ah, bh.x, bh.y);
                mma16816(acc[j], ah, bl.x, bl.y);
                mma16816(acc[j], al, bh.x, bh.y);
            }
        }

        if (chunk == 1) {
            const int row0 = (bid + tIdx * grid) << 7;
            const int r = row0 + warp_m * 16 + qrow;
#pragma unroll
            for (int j = 0; j < 8; ++j) {
                const int col = warp_n * 64 + j * 8 + (lane & 3) * 2;
                float2 v0 = make_float2(acc[j][0], acc[j][1]);
                float2 v1 = make_float2(acc[j][2], acc[j][3]);
                if (EPI == 1) {
                    float2 bv = *reinterpret_cast<const float2*>(bias + col);
                    if (r < M) {
                        float2 a0 = __ldg(reinterpret_cast<const float2*>(
                                          addend + (size_t)r * 128 + col));
                        v0.x = fmaxf(v0.x + a0.x + bv.x, 0.f);
                        v0.y = fmaxf(v0.y + a0.y + bv.y, 0.f);
                    }
                    if (r + 8 < M) {
                        float2 a1 = __ldg(reinterpret_cast<const float2*>(
                                          addend + (size_t)(r + 8) * 128 + col));
                        v1.x = fmaxf(v1.x + a1.x + bv.x, 0.f);
                        v1.y = fmaxf(v1.y + a1.y + bv.y, 0.f);
                    }
                }
                if (r < M)
                    *reinterpret_cast<float2*>(out + (size_t)r * 128 + col) = v0;
                if (r + 8 < M)
                    *reinterpret_cast<float2*>(out + (size_t)(r + 8) * 128 + col) = v1;
                acc[j][0] = acc[j][1] = acc[j][2] = acc[j][3] = 0.f;
            }
        }
    }
}

// ===========================================================================
// CSR build: histogram -> 3-phase exclusive scan -> slot fill
// ===========================================================================
__global__ void zero_deg_kernel(int* deg, int n) {
    int i = blockIdx.x * blockDim.x + threadIdx.x;
    if (i < n) deg[i] = 0;
}

__global__ void hist_kernel(const int* __restrict__ ei, int* __restrict__ deg, int E) {
    int e = blockIdx.x * blockDim.x + threadIdx.x;
    if (e >= E) return;
    int d = __ldg(&ei[E + e]);
    if ((unsigned)d < NN) atomicAdd(&deg[d], 1);
}

__global__ void scan1_kernel(const int* __restrict__ deg, int* __restrict__ excl,
                             int* __restrict__ bsum, int n) {
    __shared__ int sh[SCAN_BLK];
    int b = blockIdx.x;
    int i = b * SCAN_BLK + threadIdx.x;
    int v = (i < n) ? deg[i] : 0;
    sh[threadIdx.x] = v;
    __syncthreads();
#pragma unroll
    for (int off = 1; off < SCAN_BLK; off <<= 1) {
        int t = (threadIdx.x >= off) ? sh[threadIdx.x - off] : 0;
        __syncthreads();
        sh[threadIdx.x] += t;
        __syncthreads();
    }
    if (i < n) excl[i] = sh[threadIdx.x] - v;
    if (threadIdx.x == SCAN_BLK - 1) bsum[b] = sh[SCAN_BLK - 1];
}

// parallel exclusive scan over NSCAN (<= 256) block sums, one block
__global__ void scan2_kernel(const int* __restrict__ bsum, int* __restrict__ boff, int nb) {
    __shared__ int sh[256];
    int t = threadIdx.x;
    int v = (t < nb) ? bsum[t] : 0;
    sh[t] = v;
    __syncthreads();
#pragma unroll
    for (int off = 1; off < 256; off <<= 1) {
        int u = (t >= off) ? sh[t - off] : 0;
        __syncthreads();
        sh[t] += u;
        __syncthreads();
    }
    if (t < nb) boff[t] = sh[t] - v;
}

__global__ void scan3_kernel(const int* __restrict__ excl, const int* __restrict__ boff,
                             int* __restrict__ rowptr, int* __restrict__ cursor, int n, int total) {
    int i = blockIdx.x * blockDim.x + threadIdx.x;
    if (i < n) {
        int v = excl[i] + boff[i / SCAN_BLK];
        rowptr[i] = v;
        cursor[i] = v;
    }
    if (i == 0) rowptr[n] = total;
}

__global__ void fill_kernel(const int* __restrict__ ei, int* __restrict__ cursor,
                            int* __restrict__ srcs, int E) {
    int e = blockIdx.x * blockDim.x + threadIdx.x;
    if (e >= E) return;
    int s = __ldg(&ei[e]);
    int d = __ldg(&ei[E + e]);
    if ((unsigned)s >= NN || (unsigned)d >= NN) return;
    int slot = atomicAdd(&cursor[d], 1);
    srcs[slot] = s;
}

// ===========================================================================
// agg1: warp per node, mean of neighbor x rows (no atomics)
// ===========================================================================
__global__ void agg1_kernel(const float* __restrict__ x,
                            const int* __restrict__ rowptr,
                            const int* __restrict__ srcs,
                            float* __restrict__ agg) {
    int gid = blockIdx.x * blockDim.x + threadIdx.x;
    int n = gid >> 5, lane = gid & 31;
    if (n >= NN) return;
    int beg = __ldg(&rowptr[n]), end = __ldg(&rowptr[n + 1]);
    float4 acc = make_float4(0.f, 0.f, 0.f, 0.f);
    for (int i = beg; i < end; ++i) {
        int s = __ldg(&srcs[i]);
        float4 v = __ldg(reinterpret_cast<const float4*>(x + (size_t)s * 128) + lane);
        acc.x += v.x; acc.y += v.y; acc.z += v.z; acc.w += v.w;
    }
    float sc = 1.f / fmaxf((float)(end - beg), 1.f);
    acc.x *= sc; acc.y *= sc; acc.z *= sc; acc.w *= sc;
    reinterpret_cast<float4*>(agg + (size_t)n * 128)[lane] = acc;
}

// layer-2 aggregation of p fused with combine: z = mean_p + q + b2
__global__ void agg2z_kernel(const float* __restrict__ pq,
                             const int* __restrict__ rowptr,
                             const int* __restrict__ srcs,
                             const float* __restrict__ b2,
                             float* __restrict__ z) {
    int gid = blockIdx.x * blockDim.x + threadIdx.x;
    int n = gid >> 5, lane = gid & 31;
    if (n >= NN) return;
    int beg = __ldg(&rowptr[n]), end = __ldg(&rowptr[n + 1]);
    float2 acc = make_float2(0.f, 0.f);
    for (int i = beg; i < end; ++i) {
        int s = __ldg(&srcs[i]);
        float2 v = __ldg(reinterpret_cast<const float2*>(pq + (size_t)s * 128) + lane);
        acc.x += v.x; acc.y += v.y;
    }
    float sc = 1.f / fmaxf((float)(end - beg), 1.f);
    float2 q = __ldg(reinterpret_cast<const float2*>(pq + (size_t)n * 128 + 64) + lane);
    float2 bv = *reinterpret_cast<const float2*>(b2 + lane * 2);
    float2 r;
    r.x = fmaf(acc.x, sc, q.x + bv.x);
    r.y = fmaf(acc.y, sc, q.y + bv.y);
    *reinterpret_cast<float2*>(z + (size_t)n * 64 + lane * 2) = r;
}

// ===========================================================================
__global__ void decode_kernel(const float* __restrict__ z,
                              const int* __restrict__ eli,
                              float* __restrict__ out, int L) {
    int gid = blockIdx.x * blockDim.x + threadIdx.x;
    int e = gid >> 5;
    int lane = gid & 31;
    if (e >= L) return;
    int a = __ldg(&eli[e]);
    int b = __ldg(&eli[L + e]);
    float s = 0.f;
    if ((unsigned)a < NN && (unsigned)b < NN) {
        float2 va = *reinterpret_cast<const float2*>(z + (size_t)a * 64 + lane * 2);
        float2 vb = *reinterpret_cast<const float2*>(z + (size_t)b * 64 + lane * 2);
        s = va.x * vb.x + va.y * vb.y;
    }
#pragma unroll
    for (int off = 16; off > 0; off >>= 1)
        s += __shfl_xor_sync(0xFFFFFFFFu, s, off);
    if (lane == 0) out[e] = s;
}

// ===========================================================================
extern "C" void kernel_launch(void* const* d_in, const int* in_sizes, int n_in,
                              void* d_out, int out_size) {
    const float* x   = (const float*)d_in[0];
    const int*   ei  = (const int*)d_in[1];
    const int*   eli = (const int*)d_in[2];
    const float* W1l = (const float*)d_in[3];
    const float* b1  = (const float*)d_in[4];
    const float* W1r = (const float*)d_in[5];
    const float* W2l = (const float*)d_in[6];
    const float* b2  = (const float*)d_in[7];
    const float* W2r = (const float*)d_in[8];
    float* out = (float*)d_out;

    float *agg, *hpre, *h, *pq, *z;
    int *deg, *excl, *bsum, *boff, *rowptr, *cursor, *srcs;
    cudaGetSymbolAddress((void**)&agg,  g_agg);
    cudaGetSymbolAddress((void**)&hpre, g_hpre);
    cudaGetSymbolAddress((void**)&h,    g_h);
    cudaGetSymbolAddress((void**)&pq,   g_pq);
    cudaGetSymbolAddress((void**)&z,    g_z);
    cudaGetSymbolAddress((void**)&deg,  g_deg);
    cudaGetSymbolAddress((void**)&excl, g_excl);
    cudaGetSymbolAddress((void**)&bsum, g_bsum);
    cudaGetSymbolAddress((void**)&boff, g_boff);
    cudaGetSymbolAddress((void**)&rowptr, g_rowptr);
    cudaGetSymbolAddress((void**)&cursor, g_cursor);
    cudaGetSymbolAddress((void**)&srcs, g_srcs);

    const int smemB = 2 * (128 * (128 * 2 + 32)) + 2 * ASZ + 1024;
    cudaFuncSetAttribute(pgemmB_kernel<0>, cudaFuncAttributeMaxDynamicSharedMemorySize, smemB);
    cudaFuncSetAttribute(pgemmB_kernel<1>, cudaFuncAttributeMaxDynamicSharedMemorySize, smemB);
    const int PGRID = 148;

    // Fork a side stream off the capture stream (graph fork-join pattern).
    // Host-side resource creation only (no device memory). Leaked on purpose:
    // kernel_launch executes host code only for the correctness + capture calls.
    cudaStream_t side;
    cudaStreamCreateWithFlags(&side, cudaStreamNonBlocking);
    cudaEvent_t ev_fork, ev_join;
    cudaEventCreateWithFlags(&ev_fork, cudaEventDisableTiming);
    cudaEventCreateWithFlags(&ev_join, cudaEventDisableTiming);

    cudaEventRecord(ev_fork, 0);
    cudaStreamWaitEvent(side, ev_fork, 0);

    // ---- side stream: self-term GEMM  h_pre = x @ W1r^T ----
    pgemmB_kernel<0><<<PGRID, 512, smemB, side>>>(
        x, W1r, W1r + 64 * 128, nullptr, nullptr, hpre, NN);
    cudaEventRecord(ev_join, side);

    // ---- main stream: CSR build + layer-1 aggregation (independent) ----
    zero_deg_kernel<<<(NN + 255) / 256, 256>>>(deg, NN);
    hist_kernel<<<(NE + 255) / 256, 256>>>(ei, deg, NE);
    scan1_kernel<<<NSCAN, SCAN_BLK>>>(deg, excl, bsum, NN);
    scan2_kernel<<<1, 256>>>(bsum, boff, NSCAN);
    scan3_kernel<<<(NN + 255) / 256, 256>>>(excl, boff, rowptr, cursor, NN, NE);
    fill_kernel<<<(NE + 255) / 256, 256>>>(ei, cursor, srcs, NE);
    agg1_kernel<<<(NN * 32 + 255) / 256, 256>>>(x, rowptr, srcs, agg);

    // ---- join, then layer-1 neighbor GEMM with fused self/bias/relu ----
    cudaStreamWaitEvent(0, ev_join, 0);
    pgemmB_kernel<1><<<PGRID, 512, smemB>>>(
        agg, W1l, W1l + 64 * 128, hpre, b1, h, NN);

    // ---- Layer 2 (projection-before-aggregation) ----
    pgemmB_kernel<0><<<PGRID, 512, smemB>>>(h, W2l, W2r, nullptr, nullptr, pq, NN);
    agg2z_kernel<<<(NN * 32 + 255) / 256, 256>>>(pq, rowptr, srcs, b2, z);

    // ---- Decode ----
    decode_kernel<<<(NL * 32 + 255) / 256, 256>>>(z, eli, out, NL);
}

// round 11
// speedup vs baseline: 1.0260x; 1.0100x over previous
#include <cuda_runtime.h>
#include <cuda_bf16.h>
#include <cstdint>

#define NN 100000
#define NE 640000
#define NL 100000
#define SCAN_BLK 512
#define NSCAN ((NN + SCAN_BLK - 1) / SCAN_BLK)

// Scratch (device globals: allocation-free rule)
__device__ float g_agg[(size_t)NN * 128];     // layer-1 mean aggregate
__device__ float g_hpre[(size_t)NN * 128];    // x @ W1r^T (self term)
__device__ float g_h[(size_t)NN * 128];
__device__ float g_pq[(size_t)NN * 128];      // [p | q] = h @ [W2l | W2r]^T
__device__ float g_z[(size_t)NN * 64];
// CSR scratch
__device__ int g_deg[NN];
__device__ int g_excl[NN];
__device__ int g_bsum[NSCAN];
__device__ int g_boff[NSCAN];
__device__ int g_rowptr[NN + 1];
__device__ int g_cursor[NN];
__device__ int g_srcs[NE];

// ---------------------------------------------------------------------------
__device__ __forceinline__ uint32_t smem_u32(const void* p) {
    uint32_t a;
    asm("{ .reg .u64 t; cvta.to.shared.u64 t, %1; cvt.u32.u64 %0, t; }" : "=r"(a) : "l"(p));
    return a;
}

__device__ __forceinline__ void cp_async16(uint32_t saddr, const void* gaddr, int src_size) {
    asm volatile("cp.async.cg.shared.global [%0], [%1], 16, %2;"
                 :: "r"(saddr), "l"(gaddr), "r"(src_size) : "memory");
}
#define CP_COMMIT() asm volatile("cp.async.commit_group;" ::: "memory")
#define CP_WAIT(N)  asm volatile("cp.async.wait_group %0;" :: "n"(N) : "memory")

// bf16 hi/lo split of a float pair, packed as 2x u32 (bf16x2)
__device__ __forceinline__ void split2(float a, float b, uint32_t& hi, uint32_t& lo) {
    __nv_bfloat162 h = __floats2bfloat162_rn(a, b);
    hi = *reinterpret_cast<uint32_t*>(&h);
    __nv_bfloat162 l = __floats2bfloat162_rn(a - __low2float(h), b - __high2float(h));
    lo = *reinterpret_cast<uint32_t*>(&l);
}

// m16n8k16 bf16 mma, fp32 accumulate in place (row.col)
__device__ __forceinline__ void mma16816(float* c, const uint32_t* a, uint32_t b0, uint32_t b1) {
    asm volatile(
        "mma.sync.aligned.m16n8k16.row.col.f32.bf16.bf16.f32 "
        "{%0,%1,%2,%3}, {%4,%5,%6,%7}, {%8,%9}, {%0,%1,%2,%3};"
        : "+f"(c[0]), "+f"(c[1]), "+f"(c[2]), "+f"(c[3])
        : "r"(a[0]), "r"(a[1]), "r"(a[2]), "r"(a[3]), "r"(b0), "r"(b1));
}

// A stage: full K=128 fp32 row (512B) + 32B pad -> conflict-free LDS.64
#define ASTR 544
#define ASZ  (128 * ASTR)   // one stage = 69632 B

// ===========================================================================
// Persistent K=128 tensor-core GEMM: out[m, 0:128] = epi( A[m,:] @ W^T )
// W rows: row<64 from Wa, else Wb (pass Wa=W, Wb=W+64*128 for a full 128-row W).
// EPI 0: identity. EPI 1: relu(acc + addend[m,col] + bias[col]).
// 512 threads / 16 warps, warp tile 16x64, cp.async 2-stage FULL-TILE pipeline
// (one iteration per M-tile), weights resident in smem as bf16 hi/lo.
// ===========================================================================
__device__ __forceinline__ void prefetchA(
    int it, int bid, int grid, int M,
    const float* __restrict__ A, uint32_t sA_u32, int tid)
{
    const int row0 = (bid + it * grid) << 7;
    const uint32_t abase = sA_u32 + (it & 1) * ASZ;
    const float* gbase = A + (size_t)row0 * 128;
#pragma unroll
    for (int s = 0; s < 8; ++s) {
        int seg = s * 512 + tid;            // 0..4095
        int r = seg >> 5, c = seg & 31;
        bool val = (row0 + r) < M;
        const float* g = gbase + (val ? ((size_t)r * 128 + c * 4) : 0);
        cp_async16(abase + r * ASTR + c * 16, g, val ? 16 : 0);
    }
    CP_COMMIT();
}

template <int EPI>
__global__ void __launch_bounds__(512, 1)
pgemmB_kernel(const float* __restrict__ A,
              const float* __restrict__ Wa, const float* __restrict__ Wb,
              const float* __restrict__ addend, const float* __restrict__ bias,
              float* __restrict__ out, int M)
{
    constexpr int K = 128;
    constexpr int BSTR = K * 2 + 32;       // 288
    constexpr int SB = 128 * BSTR;         // 36864

    extern __shared__ uint8_t smem[];
    uint8_t* sBh = smem;
    uint8_t* sBl = smem + SB;
    uint8_t* sA  = smem + 2 * SB;

    const int tid = threadIdx.x, lane = tid & 31, wid = tid >> 5;
    const int warp_m = wid & 7, warp_n = wid >> 3;
    const int qrow = lane >> 2;
    const int bid = blockIdx.x, grid = gridDim.x;
    const uint32_t sA_u32 = smem_u32(smem) + 2 * SB;

    // convert weights once: bf16 hi/lo, k16-group word-permuted
    for (int idx = tid; idx < 128 * (K / 4); idx += 512) {
        int row = idx / (K / 4);
        int k = (idx % (K / 4)) * 4;
        const float* wsrc = ((row < 64) ? (Wa + (size_t)row * 128)
                                        : (Wb + (size_t)(row - 64) * 128)) + k;
        float4 v = __ldg(reinterpret_cast<const float4*>(wsrc));
        uint32_t h01, l01, h23, l23;
        split2(v.x, v.y, h01, l01);
        split2(v.z, v.w, h23, l23);
        const int base = row * BSTR + (k >> 4) * 32;
        const int km = k & 15;
        const int p0 = (km == 0) ? 0 : (km == 4) ? 16 : (km == 8) ? 4 : 20;
        *reinterpret_cast<uint32_t*>(sBh + base + p0)     = h01;
        *reinterpret_cast<uint32_t*>(sBh + base + p0 + 8) = h23;
        *reinterpret_cast<uint32_t*>(sBl + base + p0)     = l01;
        *reinterpret_cast<uint32_t*>(sBl + base + p0 + 8) = l23;
    }

    const int ntiles = (M + 127) >> 7;
    if (bid >= ntiles) return;
    const int nIter = (ntiles - bid + grid - 1) / grid;   // tiles for this CTA

    float acc[8][4] = {};

    prefetchA(0, bid, grid, M, A, sA_u32, tid);

    for (int it = 0; it < nIter; ++it) {
        if (it) __syncthreads();   // protect smem stage reuse
        if (it + 1 < nIter) {
            prefetchA(it + 1, bid, grid, M, A, sA_u32, tid);
            CP_WAIT(1);
        } else {
            CP_WAIT(0);
        }
        __syncthreads();

        const uint8_t* aS = sA + (it & 1) * ASZ;

#pragma unroll
        for (int s = 0; s < 8; ++s) {
            uint32_t ah[4], al[4];
            {
                const int rb = (warp_m * 16 + qrow) * ASTR + (s * 16 + (lane & 3) * 2) * 4;
                float2 p0 = *reinterpret_cast<const float2*>(aS + rb);
                float2 p8 = *reinterpret_cast<const float2*>(aS + rb + 8 * ASTR);
                float2 u0 = *reinterpret_cast<const float2*>(aS + rb + 32);
                float2 u8 = *reinterpret_cast<const float2*>(aS + rb + 8 * ASTR + 32);
                split2(p0.x, p0.y, ah[0], al[0]);
                split2(p8.x, p8.y, ah[1], al[1]);
                split2(u0.x, u0.y, ah[2], al[2]);
                split2(u8.x, u8.y, ah[3], al[3]);
            }
            const int gk32 = s * 32 + (lane & 3) * 8;
#pragma unroll
            for (int j = 0; j < 8; ++j) {
                const int nb = (warp_n * 64 + j * 8 + qrow) * BSTR + gk32;
                uint2 bh = *reinterpret_cast<const uint2*>(sBh + nb);
                uint2 bl = *reinterpret_cast<const uint2*>(sBl + nb);
                mma16816(acc[j], ah, bh.x, bh.y);
                mma16816(acc[j], ah, bl.x, bl.y);
                mma16816(acc[j], al, bh.x, bh.y);
            }
        }

        // epilogue every iteration (one full tile per iter)
        {
            const int row0 = (bid + it * grid) << 7;
            const int r = row0 + warp_m * 16 + qrow;
#pragma unroll
            for (int j = 0; j < 8; ++j) {
                const int col = warp_n * 64 + j * 8 + (lane & 3) * 2;
                float2 v0 = make_float2(acc[j][0], acc[j][1]);
                float2 v1 = make_float2(acc[j][2], acc[j][3]);
                if (EPI == 1) {
                    float2 bv = *reinterpret_cast<const float2*>(bias + col);
                    if (r < M) {
                        float2 a0 = __ldg(reinterpret_cast<const float2*>(
                                          addend + (size_t)r * 128 + col));
                        v0.x = fmaxf(v0.x + a0.x + bv.x, 0.f);
                        v0.y = fmaxf(v0.y + a0.y + bv.y, 0.f);
                    }
                    if (r + 8 < M) {
                        float2 a1 = __ldg(reinterpret_cast<const float2*>(
                                          addend + (size_t)(r + 8) * 128 + col));
                        v1.x = fmaxf(v1.x + a1.x + bv.x, 0.f);
                        v1.y = fmaxf(v1.y + a1.y + bv.y, 0.f);
                    }
                }
                if (r < M)
                    *reinterpret_cast<float2*>(out + (size_t)r * 128 + col) = v0;
                if (r + 8 < M)
                    *reinterpret_cast<float2*>(out + (size_t)(r + 8) * 128 + col) = v1;
                acc[j][0] = acc[j][1] = acc[j][2] = acc[j][3] = 0.f;
            }
        }
    }
}

// ===========================================================================
// CSR build: histogram -> 3-phase exclusive scan -> slot fill
// ===========================================================================
__global__ void zero_deg_kernel(int* deg, int n) {
    int i = blockIdx.x * blockDim.x + threadIdx.x;
    if (i < n) deg[i] = 0;
}

__global__ void hist_kernel(const int* __restrict__ ei, int* __restrict__ deg, int E) {
    int e = blockIdx.x * blockDim.x + threadIdx.x;
    if (e >= E) return;
    int d = __ldg(&ei[E + e]);
    if ((unsigned)d < NN) atomicAdd(&deg[d], 1);
}

__global__ void scan1_kernel(const int* __restrict__ deg, int* __restrict__ excl,
                             int* __restrict__ bsum, int n) {
    __shared__ int sh[SCAN_BLK];
    int b = blockIdx.x;
    int i = b * SCAN_BLK + threadIdx.x;
    int v = (i < n) ? deg[i] : 0;
    sh[threadIdx.x] = v;
    __syncthreads();
#pragma unroll
    for (int off = 1; off < SCAN_BLK; off <<= 1) {
        int t = (threadIdx.x >= off) ? sh[threadIdx.x - off] : 0;
        __syncthreads();
        sh[threadIdx.x] += t;
        __syncthreads();
    }
    if (i < n) excl[i] = sh[threadIdx.x] - v;
    if (threadIdx.x == SCAN_BLK - 1) bsum[b] = sh[SCAN_BLK - 1];
}

// parallel exclusive scan over NSCAN (<= 256) block sums, one block
__global__ void scan2_kernel(const int* __restrict__ bsum, int* __restrict__ boff, int nb) {
    __shared__ int sh[256];
    int t = threadIdx.x;
    int v = (t < nb) ? bsum[t] : 0;
    sh[t] = v;
    __syncthreads();
#pragma unroll
    for (int off = 1; off < 256; off <<= 1) {
        int u = (t >= off) ? sh[t - off] : 0;
        __syncthreads();
        sh[t] += u;
        __syncthreads();
    }
    if (t < nb) boff[t] = sh[t] - v;
}

__global__ void scan3_kernel(const int* __restrict__ excl, const int* __restrict__ boff,
                             int* __restrict__ rowptr, int* __restrict__ cursor, int n, int total) {
    int i = blockIdx.x * blockDim.x + threadIdx.x;
    if (i < n) {
        int v = excl[i] + boff[i / SCAN_BLK];
        rowptr[i] = v;
        cursor[i] = v;
    }
    if (i == 0) rowptr[n] = total;
}

__global__ void fill_kernel(const int* __restrict__ ei, int* __restrict__ cursor,
                            int* __restrict__ srcs, int E) {
    int e = blockIdx.x * blockDim.x + threadIdx.x;
    if (e >= E) return;
    int s = __ldg(&ei[e]);
    int d = __ldg(&ei[E + e]);
    if ((unsigned)s >= NN || (unsigned)d >= NN) return;
    int slot = atomicAdd(&cursor[d], 1);
    srcs[slot] = s;
}

// ===========================================================================
// agg1: warp per node, mean of neighbor x rows (no atomics; L2-roofline bound)
// ===========================================================================
__global__ void agg1_kernel(const float* __restrict__ x,
                            const int* __restrict__ rowptr,
                            const int* __restrict__ srcs,
                            float* __restrict__ agg) {
    int gid = blockIdx.x * blockDim.x + threadIdx.x;
    int n = gid >> 5, lane = gid & 31;
    if (n >= NN) return;
    int beg = __ldg(&rowptr[n]), end = __ldg(&rowptr[n + 1]);
    float4 acc = make_float4(0.f, 0.f, 0.f, 0.f);
    for (int i = beg; i < end; ++i) {
        int s = __ldg(&srcs[i]);
        float4 v = __ldg(reinterpret_cast<const float4*>(x + (size_t)s * 128) + lane);
        acc.x += v.x; acc.y += v.y; acc.z += v.z; acc.w += v.w;
    }
    float sc = 1.f / fmaxf((float)(end - beg), 1.f);
    acc.x *= sc; acc.y *= sc; acc.z *= sc; acc.w *= sc;
    reinterpret_cast<float4*>(agg + (size_t)n * 128)[lane] = acc;
}

// layer-2 aggregation of p fused with combine: z = mean_p + q + b2
__global__ void agg2z_kernel(const float* __restrict__ pq,
                             const int* __restrict__ rowptr,
                             const int* __restrict__ srcs,
                             const float* __restrict__ b2,
                             float* __restrict__ z) {
    int gid = blockIdx.x * blockDim.x + threadIdx.x;
    int n = gid >> 5, lane = gid & 31;
    if (n >= NN) return;
    int beg = __ldg(&rowptr[n]), end = __ldg(&rowptr[n + 1]);
    float2 acc = make_float2(0.f, 0.f);
    for (int i = beg; i < end; ++i) {
        int s = __ldg(&srcs[i]);
        float2 v = __ldg(reinterpret_cast<const float2*>(pq + (size_t)s * 128) + lane);
        acc.x += v.x; acc.y += v.y;
    }
    float sc = 1.f / fmaxf((float)(end - beg), 1.f);
    float2 q = __ldg(reinterpret_cast<const float2*>(pq + (size_t)n * 128 + 64) + lane);
    float2 bv = *reinterpret_cast<const float2*>(b2 + lane * 2);
    float2 r;
    r.x = fmaf(acc.x, sc, q.x + bv.x);
    r.y = fmaf(acc.y, sc, q.y + bv.y);
    *reinterpret_cast<float2*>(z + (size_t)n * 64 + lane * 2) = r;
}

// ===========================================================================
// Decode: half-warp per pair, float4 loads (4x fewer load instrs per pair)
// ===========================================================================
__global__ void decode_kernel(const float* __restrict__ z,
                              const int* __restrict__ eli,
                              float* __restrict__ out, int L) {
    int gid = blockIdx.x * blockDim.x + threadIdx.x;
    int e = gid >> 4;
    int l = gid & 15;
    if (e >= L) return;
    int a = __ldg(&eli[e]);
    int b = __ldg(&eli[L + e]);
    float s = 0.f;
    if ((unsigned)a < NN && (unsigned)b < NN) {
        float4 va = __ldg(reinterpret_cast<const float4*>(z + (size_t)a * 64) + l);
        float4 vb = __ldg(reinterpret_cast<const float4*>(z + (size_t)b * 64) + l);
        s = va.x * vb.x + va.y * vb.y + va.z * vb.z + va.w * vb.w;
    }
#pragma unroll
    for (int off = 8; off > 0; off >>= 1)
        s += __shfl_xor_sync(0xFFFFFFFFu, s, off);
    if (l == 0) out[e] = s;
}

// ===========================================================================
extern "C" void kernel_launch(void* const* d_in, const int* in_sizes, int n_in,
                              void* d_out, int out_size) {
    const float* x   = (const float*)d_in[0];
    const int*   ei  = (const int*)d_in[1];
    const int*   eli = (const int*)d_in[2];
    const float* W1l = (const float*)d_in[3];
    const float* b1  = (const float*)d_in[4];
    const float* W1r = (const float*)d_in[5];
    const float* W2l = (const float*)d_in[6];
    const float* b2  = (const float*)d_in[7];
    const float* W2r = (const float*)d_in[8];
    float* out = (float*)d_out;

    float *agg, *hpre, *h, *pq, *z;
    int *deg, *excl, *bsum, *boff, *rowptr, *cursor, *srcs;
    cudaGetSymbolAddress((void**)&agg,  g_agg);
    cudaGetSymbolAddress((void**)&hpre, g_hpre);
    cudaGetSymbolAddress((void**)&h,    g_h);
    cudaGetSymbolAddress((void**)&pq,   g_pq);
    cudaGetSymbolAddress((void**)&z,    g_z);
    cudaGetSymbolAddress((void**)&deg,  g_deg);
    cudaGetSymbolAddress((void**)&excl, g_excl);
    cudaGetSymbolAddress((void**)&bsum, g_bsum);
    cudaGetSymbolAddress((void**)&boff, g_boff);
    cudaGetSymbolAddress((void**)&rowptr, g_rowptr);
    cudaGetSymbolAddress((void**)&cursor, g_cursor);
    cudaGetSymbolAddress((void**)&srcs, g_srcs);

    // smem: B hi/lo (73728) + 2 full-K A stages (139264) + pad
    const int smemB = 2 * (128 * (128 * 2 + 32)) + 2 * ASZ + 256;   // 213,248
    cudaFuncSetAttribute(pgemmB_kernel<0>, cudaFuncAttributeMaxDynamicSharedMemorySize, smemB);
    cudaFuncSetAttribute(pgemmB_kernel<1>, cudaFuncAttributeMaxDynamicSharedMemorySize, smemB);
    const int PGRID = 148;

    // Fork a side stream off the capture stream (graph fork-join pattern).
    cudaStream_t side;
    cudaStreamCreateWithFlags(&side, cudaStreamNonBlocking);
    cudaEvent_t ev_fork, ev_join;
    cudaEventCreateWithFlags(&ev_fork, cudaEventDisableTiming);
    cudaEventCreateWithFlags(&ev_join, cudaEventDisableTiming);

    cudaEventRecord(ev_fork, 0);
    cudaStreamWaitEvent(side, ev_fork, 0);

    // ---- side stream: self-term GEMM  h_pre = x @ W1r^T ----
    pgemmB_kernel<0><<<PGRID, 512, smemB, side>>>(
        x, W1r, W1r + 64 * 128, nullptr, nullptr, hpre, NN);
    cudaEventRecord(ev_join, side);

    // ---- main stream: CSR build + layer-1 aggregation (independent) ----
    zero_deg_kernel<<<(NN + 255) / 256, 256>>>(deg, NN);
    hist_kernel<<<(NE + 255) / 256, 256>>>(ei, deg, NE);
    scan1_kernel<<<NSCAN, SCAN_BLK>>>(deg, excl, bsum, NN);
    scan2_kernel<<<1, 256>>>(bsum, boff, NSCAN);
    scan3_kernel<<<(NN + 255) / 256, 256>>>(excl, boff, rowptr, cursor, NN, NE);
    fill_kernel<<<(NE + 255) / 256, 256>>>(ei, cursor, srcs, NE);
    agg1_kernel<<<(NN * 32 + 255) / 256, 256>>>(x, rowptr, srcs, agg);

    // ---- join, then layer-1 neighbor GEMM with fused self/bias/relu ----
    cudaStreamWaitEvent(0, ev_join, 0);
    pgemmB_kernel<1><<<PGRID, 512, smemB>>>(
        agg, W1l, W1l + 64 * 128, hpre, b1, h, NN);

    // ---- Layer 2 (projection-before-aggregation) ----
    pgemmB_kernel<0><<<PGRID, 512, smemB>>>(h, W2l, W2r, nullptr, nullptr, pq, NN);
    agg2z_kernel<<<(NN * 32 + 255) / 256, 256>>>(pq, rowptr, srcs, b2, z);

    // ---- Decode ----
    decode_kernel<<<(NL * 16 + 255) / 256, 256>>>(z, eli, out, NL);
}